// round 1
// baseline (speedup 1.0000x reference)
#include <cuda_runtime.h>
#include <cuda_bf16.h>
#include <cstdint>

// Problem constants
#define TOK 4096   // B*S tokens
#define HD  1024   // hidden
#define NE  8      // experts
#define FF  4096   // ffn dim
#define TOPK 2

// ---------------- scratch (device globals; no allocation) ----------------
__device__ int   g_counts[NE];
__device__ int   g_base[NE];
__device__ int   g_tok[NE][TOK];          // token list per expert
__device__ int   g_sel_e[TOK * TOPK];     // per-token selected expert
__device__ int   g_sel_s[TOK * TOPK];     // per-token slot within expert
__device__ float g_sel_w[TOK * TOPK];     // per-token renormalized weight
__device__ float g_h[(size_t)TOK * TOPK * FF];  // SwiGLU activations (8192 x 4096) 134MB
__device__ float g_y[(size_t)TOK * TOPK * HD];  // down-proj outputs  (8192 x 1024) 33MB

// ---------------- kernel 0: zero counters ----------------
__global__ void zero_counts_kernel() {
    if (threadIdx.x < NE) g_counts[threadIdx.x] = 0;
}

// ---------------- kernel 1: routing (top-2 of 8 logits) ----------------
// one block per token, 256 threads = 8 warps; warp e computes logit e
__global__ void routing_kernel(const float* __restrict__ x,
                               const float* __restrict__ Wg,
                               const float* __restrict__ bg) {
    const int t   = blockIdx.x;
    const int tid = threadIdx.x;
    const int wid = tid >> 5;
    const int lid = tid & 31;

    __shared__ float s_logit[NE];

    const float* xt = x + (size_t)t * HD;
    float acc = 0.f;
    // lane l sums h = l, l+32, ... ; Wg is [H, E] row-major
    for (int h = lid; h < HD; h += 32)
        acc += xt[h] * Wg[h * NE + wid];
    // warp reduce
    #pragma unroll
    for (int o = 16; o > 0; o >>= 1)
        acc += __shfl_down_sync(0xFFFFFFFFu, acc, o);
    if (lid == 0) s_logit[wid] = acc + bg[wid];
    __syncthreads();

    if (tid == 0) {
        float l[NE];
        #pragma unroll
        for (int e = 0; e < NE; e++) l[e] = s_logit[e];
        int i0 = 0;
        #pragma unroll
        for (int e = 1; e < NE; e++) if (l[e] > l[i0]) i0 = e;
        int i1 = (i0 == 0) ? 1 : 0;
        #pragma unroll
        for (int e = 0; e < NE; e++)
            if (e != i0 && l[e] > l[i1]) i1 = e;

        // softmax top-2 renormalized: denominators cancel
        float w1 = __expf(l[i1] - l[i0]);     // <= 1
        float inv = 1.f / (1.f + w1);
        float wn0 = inv;
        float wn1 = w1 * inv;

        int s0 = atomicAdd(&g_counts[i0], 1);
        int s1 = atomicAdd(&g_counts[i1], 1);
        g_tok[i0][s0] = t;
        g_tok[i1][s1] = t;
        g_sel_e[t * 2 + 0] = i0;  g_sel_s[t * 2 + 0] = s0;  g_sel_w[t * 2 + 0] = wn0;
        g_sel_e[t * 2 + 1] = i1;  g_sel_s[t * 2 + 1] = s1;  g_sel_w[t * 2 + 1] = wn1;
    }
}

// ---------------- kernel 2: exclusive-scan bases ----------------
__global__ void bases_kernel() {
    if (threadIdx.x == 0) {
        int b = 0;
        #pragma unroll
        for (int e = 0; e < NE; e++) { g_base[e] = b; b += g_counts[e]; }
    }
}

// ---------------- kernel 3: fused gate/up GEMM + SwiGLU ----------------
// C-tile 64x64 (tokens x F), BK=16, 256 threads, 4x4 per-thread, two outputs
__global__ __launch_bounds__(256) void gemm1_kernel(const float* __restrict__ x,
                                                    const float* __restrict__ W1,
                                                    const float* __restrict__ W3) {
    const int e = blockIdx.z;
    const int n = g_counts[e];
    const int m0 = blockIdx.y * 64;
    if (m0 >= n) return;
    const int n0 = blockIdx.x * 64;
    const int base = g_base[e];

    __shared__ float As[16][68];     // [k][m], padded
    __shared__ float B1s[16][64];    // [k][n]
    __shared__ float B3s[16][64];
    __shared__ int   toks[64];

    const int tid = threadIdx.x;
    if (tid < 64) {
        int r = m0 + tid;
        toks[tid] = g_tok[e][r < n ? r : (n - 1)];
    }
    __syncthreads();

    const int tx = tid & 15;         // C col group
    const int ty = tid >> 4;         // C row group
    const int arow = tid >> 2;       // 0..63
    const int akq  = tid & 3;        // float4 index in K
    const int bk   = tid >> 4;       // 0..15
    const int bnq  = tid & 15;       // 0..15

    const float* __restrict__ B1 = W1 + (size_t)e * HD * FF;
    const float* __restrict__ B3 = W3 + (size_t)e * HD * FF;
    const float* arow_ptr = x + (size_t)toks[arow] * HD + akq * 4;

    float cg[4][4] = {};
    float cu[4][4] = {};

    for (int k0 = 0; k0 < HD; k0 += 16) {
        float4 av = *(const float4*)(arow_ptr + k0);
        As[akq * 4 + 0][arow] = av.x;
        As[akq * 4 + 1][arow] = av.y;
        As[akq * 4 + 2][arow] = av.z;
        As[akq * 4 + 3][arow] = av.w;
        *(float4*)&B1s[bk][bnq * 4] =
            *(const float4*)(B1 + (size_t)(k0 + bk) * FF + n0 + bnq * 4);
        *(float4*)&B3s[bk][bnq * 4] =
            *(const float4*)(B3 + (size_t)(k0 + bk) * FF + n0 + bnq * 4);
        __syncthreads();

        #pragma unroll
        for (int k = 0; k < 16; k++) {
            float4 a  = *(const float4*)&As[k][ty * 4];
            float4 b1 = *(const float4*)&B1s[k][tx * 4];
            float4 b3 = *(const float4*)&B3s[k][tx * 4];
            const float aa[4] = {a.x, a.y, a.z, a.w};
            const float bb1[4] = {b1.x, b1.y, b1.z, b1.w};
            const float bb3[4] = {b3.x, b3.y, b3.z, b3.w};
            #pragma unroll
            for (int i = 0; i < 4; i++)
                #pragma unroll
                for (int j = 0; j < 4; j++) {
                    cg[i][j] += aa[i] * bb1[j];
                    cu[i][j] += aa[i] * bb3[j];
                }
        }
        __syncthreads();
    }

    // epilogue: h = silu(g) * u
    #pragma unroll
    for (int i = 0; i < 4; i++) {
        int r = m0 + ty * 4 + i;
        if (r >= n) continue;
        float* hp = g_h + (size_t)(base + r) * FF + n0 + tx * 4;
        #pragma unroll
        for (int j = 0; j < 4; j++) {
            float g = cg[i][j];
            float s = g / (1.f + __expf(-g));
            hp[j] = s * cu[i][j];
        }
    }
}

// ---------------- kernel 4: down-proj GEMM ----------------
// C-tile 64x64 (rows x H), BK=16
__global__ __launch_bounds__(256) void gemm2_kernel(const float* __restrict__ W2) {
    const int e = blockIdx.z;
    const int n = g_counts[e];
    const int m0 = blockIdx.y * 64;
    if (m0 >= n) return;
    const int n0 = blockIdx.x * 64;
    const int base = g_base[e];

    __shared__ float As[16][68];
    __shared__ float Bs[16][64];

    const int tid = threadIdx.x;
    const int tx = tid & 15;
    const int ty = tid >> 4;
    const int arow = tid >> 2;
    const int akq  = tid & 3;
    const int bk   = tid >> 4;
    const int bnq  = tid & 15;

    const float* __restrict__ B = W2 + (size_t)e * FF * HD;
    const int ar = m0 + arow;
    const float* arow_ptr = g_h + (size_t)(base + (ar < n ? ar : (n - 1))) * FF + akq * 4;

    float c[4][4] = {};

    for (int k0 = 0; k0 < FF; k0 += 16) {
        float4 av = *(const float4*)(arow_ptr + k0);
        As[akq * 4 + 0][arow] = av.x;
        As[akq * 4 + 1][arow] = av.y;
        As[akq * 4 + 2][arow] = av.z;
        As[akq * 4 + 3][arow] = av.w;
        *(float4*)&Bs[bk][bnq * 4] =
            *(const float4*)(B + (size_t)(k0 + bk) * HD + n0 + bnq * 4);
        __syncthreads();

        #pragma unroll
        for (int k = 0; k < 16; k++) {
            float4 a = *(const float4*)&As[k][ty * 4];
            float4 b = *(const float4*)&Bs[k][tx * 4];
            const float aa[4] = {a.x, a.y, a.z, a.w};
            const float bb[4] = {b.x, b.y, b.z, b.w};
            #pragma unroll
            for (int i = 0; i < 4; i++)
                #pragma unroll
                for (int j = 0; j < 4; j++)
                    c[i][j] += aa[i] * bb[j];
        }
        __syncthreads();
    }

    #pragma unroll
    for (int i = 0; i < 4; i++) {
        int r = m0 + ty * 4 + i;
        if (r >= n) continue;
        float* yp = g_y + (size_t)(base + r) * HD + n0 + tx * 4;
        #pragma unroll
        for (int j = 0; j < 4; j++) yp[j] = c[i][j];
    }
}

// ---------------- kernel 5: weighted combine ----------------
__global__ void combine_kernel(float* __restrict__ out) {
    const int idx = blockIdx.x * blockDim.x + threadIdx.x;   // over TOK * HD/4
    const int t  = idx / (HD / 4);
    const int c4 = idx % (HD / 4);

    float4 acc = make_float4(0.f, 0.f, 0.f, 0.f);
    #pragma unroll
    for (int k = 0; k < TOPK; k++) {
        int   e = g_sel_e[t * 2 + k];
        int   s = g_sel_s[t * 2 + k];
        float w = g_sel_w[t * 2 + k];
        const float4 v = *(const float4*)(g_y + (size_t)(g_base[e] + s) * HD + c4 * 4);
        acc.x += w * v.x; acc.y += w * v.y; acc.z += w * v.z; acc.w += w * v.w;
    }
    *(float4*)(out + (size_t)t * HD + c4 * 4) = acc;
}

// ---------------- launcher ----------------
extern "C" void kernel_launch(void* const* d_in, const int* in_sizes, int n_in,
                              void* d_out, int out_size) {
    const float* x  = (const float*)d_in[0];   // [B,S,H] = [4096,1024]
    const float* Wg = (const float*)d_in[1];   // [H,E]
    const float* bg = (const float*)d_in[2];   // [E]
    const float* W1 = (const float*)d_in[3];   // [E,H,F]
    const float* W3 = (const float*)d_in[4];   // [E,H,F]
    const float* W2 = (const float*)d_in[5];   // [E,F,H]
    float* out = (float*)d_out;                // [4096,1024]

    zero_counts_kernel<<<1, 32>>>();
    routing_kernel<<<TOK, 256>>>(x, Wg, bg);
    bases_kernel<<<1, 1>>>();
    gemm1_kernel<<<dim3(FF / 64, TOK / 64, NE), 256>>>(x, W1, W3);
    gemm2_kernel<<<dim3(HD / 64, TOK / 64, NE), 256>>>(W2);
    combine_kernel<<<(TOK * (HD / 4)) / 256, 256>>>(out);
}

// round 3
// speedup vs baseline: 1.2929x; 1.2929x over previous
#include <cuda_runtime.h>
#include <cstdint>

#define TOK 4096   // B*S tokens
#define HD  1024
#define NE  8
#define FF  4096
#define TOPK 2

// ---------------- scratch (device globals) ----------------
__device__ int   g_counts[NE];
__device__ int   g_base[NE];
__device__ int   g_tok[NE][TOK];
__device__ int   g_sel_e[TOK * TOPK];
__device__ int   g_sel_s[TOK * TOPK];
__device__ float g_sel_w[TOK * TOPK];
__device__ float g_h[(size_t)TOK * TOPK * FF];
__device__ float g_y[(size_t)TOK * TOPK * HD];

// ---------------- helpers ----------------
__device__ __forceinline__ uint32_t f2tf(float f) {
    uint32_t u; asm("cvt.rna.tf32.f32 %0, %1;" : "=r"(u) : "f"(f)); return u;
}
__device__ __forceinline__ void mma8(float* d, const uint32_t* a, const uint32_t* b) {
    asm volatile("mma.sync.aligned.m16n8k8.row.col.f32.tf32.tf32.f32 "
        "{%0,%1,%2,%3}, {%4,%5,%6,%7}, {%8,%9}, {%0,%1,%2,%3};"
        : "+f"(d[0]), "+f"(d[1]), "+f"(d[2]), "+f"(d[3])
        : "r"(a[0]), "r"(a[1]), "r"(a[2]), "r"(a[3]), "r"(b[0]), "r"(b[1]));
}

// ---------------- kernel 0: zero counters ----------------
__global__ void zero_counts_kernel() {
    if (threadIdx.x < NE) g_counts[threadIdx.x] = 0;
}

// ---------------- kernel 1: routing ----------------
__global__ void routing_kernel(const float* __restrict__ x,
                               const float* __restrict__ Wg,
                               const float* __restrict__ bg) {
    const int t = blockIdx.x, tid = threadIdx.x, wid = tid >> 5, lid = tid & 31;
    __shared__ float s_logit[NE];
    const float* xt = x + (size_t)t * HD;
    float acc = 0.f;
    for (int h = lid; h < HD; h += 32) acc += xt[h] * Wg[h * NE + wid];
    #pragma unroll
    for (int o = 16; o > 0; o >>= 1) acc += __shfl_down_sync(0xFFFFFFFFu, acc, o);
    if (lid == 0) s_logit[wid] = acc + bg[wid];
    __syncthreads();
    if (tid == 0) {
        float l[NE];
        #pragma unroll
        for (int e = 0; e < NE; e++) l[e] = s_logit[e];
        int i0 = 0;
        #pragma unroll
        for (int e = 1; e < NE; e++) if (l[e] > l[i0]) i0 = e;
        int i1 = (i0 == 0) ? 1 : 0;
        #pragma unroll
        for (int e = 0; e < NE; e++) if (e != i0 && l[e] > l[i1]) i1 = e;
        float w1 = __expf(l[i1] - l[i0]);
        float inv = 1.f / (1.f + w1);
        int s0 = atomicAdd(&g_counts[i0], 1);
        int s1 = atomicAdd(&g_counts[i1], 1);
        g_tok[i0][s0] = t;  g_tok[i1][s1] = t;
        g_sel_e[t*2+0] = i0; g_sel_s[t*2+0] = s0; g_sel_w[t*2+0] = inv;
        g_sel_e[t*2+1] = i1; g_sel_s[t*2+1] = s1; g_sel_w[t*2+1] = w1 * inv;
    }
}

// ---------------- kernel 2: bases ----------------
__global__ void bases_kernel() {
    if (threadIdx.x == 0) {
        int b = 0;
        #pragma unroll
        for (int e = 0; e < NE; e++) { g_base[e] = b; b += g_counts[e]; }
    }
}

#define AP 132   // padded row length (floats) for 128-wide smem tiles
#define BP 68    // padded row length for 64-wide smem tiles

// ---------------- GEMM1: tf32 mma, fused W1/W3 + SwiGLU ----------------
// CTA 128M x 64N, BK=32. 8 warps as 4(M) x 2(N); warp tile 32x32
// (2 mtiles of 16 x 4 ntiles of 8). Dual accumulators (gate, up).
__global__ __launch_bounds__(256) void gemm1_mma(const float* __restrict__ x,
                                                 const float* __restrict__ W1,
                                                 const float* __restrict__ W3) {
    const int e  = blockIdx.z;
    const int n  = g_counts[e];
    const int m0 = blockIdx.y * 128;
    if (m0 >= n) return;
    const int n0   = blockIdx.x * 64;
    const int base = g_base[e];

    __shared__ uint32_t As[32][AP];
    __shared__ uint32_t B1s[32][BP];
    __shared__ uint32_t B3s[32][BP];
    __shared__ int toks[128];

    const int tid = threadIdx.x, wid = tid >> 5, lane = tid & 31;
    const int g = lane >> 2, tig = lane & 3;
    const int wm = wid >> 1, wn = wid & 1;

    if (tid < 128) { int r = m0 + tid; toks[tid] = g_tok[e][r < n ? r : n - 1]; }
    __syncthreads();

    const float* __restrict__ B1g = W1 + (size_t)e * HD * FF;
    const float* __restrict__ B3g = W3 + (size_t)e * HD * FF;

    float cg[2][4][4] = {};
    float cu[2][4][4] = {};

    for (int k0 = 0; k0 < HD; k0 += 32) {
        // A: 128 rows x 32 k (gathered token rows)
        #pragma unroll
        for (int q = 0; q < 4; q++) {
            int idx = q * 256 + tid, row = idx >> 3, kq = idx & 7;
            float4 v = *(const float4*)(x + (size_t)toks[row] * HD + k0 + kq * 4);
            As[kq * 4 + 0][row] = f2tf(v.x);
            As[kq * 4 + 1][row] = f2tf(v.y);
            As[kq * 4 + 2][row] = f2tf(v.z);
            As[kq * 4 + 3][row] = f2tf(v.w);
        }
        // B1/B3: 32 k x 64 n
        #pragma unroll
        for (int q = 0; q < 2; q++) {
            int idx = q * 256 + tid, kl = idx >> 4, nq = idx & 15;
            size_t go = (size_t)(k0 + kl) * FF + n0 + nq * 4;
            float4 v1 = *(const float4*)(B1g + go);
            float4 v3 = *(const float4*)(B3g + go);
            uint4 s1 = make_uint4(f2tf(v1.x), f2tf(v1.y), f2tf(v1.z), f2tf(v1.w));
            uint4 s3 = make_uint4(f2tf(v3.x), f2tf(v3.y), f2tf(v3.z), f2tf(v3.w));
            *(uint4*)&B1s[kl][nq * 4] = s1;
            *(uint4*)&B3s[kl][nq * 4] = s3;
        }
        __syncthreads();

        #pragma unroll
        for (int ks = 0; ks < 4; ks++) {
            const int kk = ks * 8;
            uint32_t a[2][4];
            #pragma unroll
            for (int mt = 0; mt < 2; mt++) {
                const int rb = wm * 32 + mt * 16;
                a[mt][0] = As[kk + tig][rb + g];
                a[mt][1] = As[kk + tig][rb + g + 8];
                a[mt][2] = As[kk + tig + 4][rb + g];
                a[mt][3] = As[kk + tig + 4][rb + g + 8];
            }
            #pragma unroll
            for (int nt = 0; nt < 4; nt++) {
                const int nb = wn * 32 + nt * 8;
                uint32_t b1[2] = { B1s[kk + tig][nb + g], B1s[kk + tig + 4][nb + g] };
                uint32_t b3[2] = { B3s[kk + tig][nb + g], B3s[kk + tig + 4][nb + g] };
                #pragma unroll
                for (int mt = 0; mt < 2; mt++) {
                    mma8(cg[mt][nt], a[mt], b1);
                    mma8(cu[mt][nt], a[mt], b3);
                }
            }
        }
        __syncthreads();
    }

    // epilogue: h = silu(g) * u
    #pragma unroll
    for (int mt = 0; mt < 2; mt++) {
        #pragma unroll
        for (int half = 0; half < 2; half++) {
            const int r = m0 + wm * 32 + mt * 16 + g + half * 8;
            if (r >= n) continue;
            float* hp = g_h + (size_t)(base + r) * FF + n0 + wn * 32 + 2 * tig;
            #pragma unroll
            for (int nt = 0; nt < 4; nt++) {
                float g0 = cg[mt][nt][half * 2 + 0], g1 = cg[mt][nt][half * 2 + 1];
                float u0 = cu[mt][nt][half * 2 + 0], u1 = cu[mt][nt][half * 2 + 1];
                float2 o;
                o.x = (g0 / (1.f + __expf(-g0))) * u0;
                o.y = (g1 / (1.f + __expf(-g1))) * u1;
                *(float2*)(hp + nt * 8) = o;
            }
        }
    }
}

// ---------------- GEMM2: tf32 mma down-proj ----------------
// CTA 128M x 128N, BK=32. 8 warps as 4(M) x 2(N); warp tile 32x64
// (2 mtiles x 8 ntiles).
__global__ __launch_bounds__(256) void gemm2_mma(const float* __restrict__ W2) {
    const int e  = blockIdx.z;
    const int n  = g_counts[e];
    const int m0 = blockIdx.y * 128;
    if (m0 >= n) return;
    const int n0   = blockIdx.x * 128;
    const int base = g_base[e];

    __shared__ uint32_t As[32][AP];
    __shared__ uint32_t Bs[32][AP];

    const int tid = threadIdx.x, wid = tid >> 5, lane = tid & 31;
    const int g = lane >> 2, tig = lane & 3;
    const int wm = wid >> 1, wn = wid & 1;

    const float* __restrict__ Bg = W2 + (size_t)e * FF * HD;

    float c[2][8][4] = {};

    for (int k0 = 0; k0 < FF; k0 += 32) {
        // A: 128 rows x 32 k from g_h
        #pragma unroll
        for (int q = 0; q < 4; q++) {
            int idx = q * 256 + tid, row = idx >> 3, kq = idx & 7;
            int rg = m0 + row; if (rg >= n) rg = n - 1;
            float4 v = *(const float4*)(g_h + (size_t)(base + rg) * FF + k0 + kq * 4);
            As[kq * 4 + 0][row] = f2tf(v.x);
            As[kq * 4 + 1][row] = f2tf(v.y);
            As[kq * 4 + 2][row] = f2tf(v.z);
            As[kq * 4 + 3][row] = f2tf(v.w);
        }
        // B: 32 k x 128 n from W2
        #pragma unroll
        for (int q = 0; q < 4; q++) {
            int idx = q * 256 + tid, kl = idx >> 5, nq = idx & 31;
            float4 v = *(const float4*)(Bg + (size_t)(k0 + kl) * HD + n0 + nq * 4);
            uint4 s = make_uint4(f2tf(v.x), f2tf(v.y), f2tf(v.z), f2tf(v.w));
            *(uint4*)&Bs[kl][nq * 4] = s;
        }
        __syncthreads();

        #pragma unroll
        for (int ks = 0; ks < 4; ks++) {
            const int kk = ks * 8;
            uint32_t a[2][4];
            #pragma unroll
            for (int mt = 0; mt < 2; mt++) {
                const int rb = wm * 32 + mt * 16;
                a[mt][0] = As[kk + tig][rb + g];
                a[mt][1] = As[kk + tig][rb + g + 8];
                a[mt][2] = As[kk + tig + 4][rb + g];
                a[mt][3] = As[kk + tig + 4][rb + g + 8];
            }
            #pragma unroll
            for (int nt = 0; nt < 8; nt++) {
                const int nb = wn * 64 + nt * 8;
                uint32_t b[2] = { Bs[kk + tig][nb + g], Bs[kk + tig + 4][nb + g] };
                #pragma unroll
                for (int mt = 0; mt < 2; mt++) {
                    mma8(c[mt][nt], a[mt], b);
                }
            }
        }
        __syncthreads();
    }

    #pragma unroll
    for (int mt = 0; mt < 2; mt++) {
        #pragma unroll
        for (int half = 0; half < 2; half++) {
            const int r = m0 + wm * 32 + mt * 16 + g + half * 8;
            if (r >= n) continue;
            float* yp = g_y + (size_t)(base + r) * HD + n0 + wn * 64 + 2 * tig;
            #pragma unroll
            for (int nt = 0; nt < 8; nt++) {
                float2 o;
                o.x = c[mt][nt][half * 2 + 0];
                o.y = c[mt][nt][half * 2 + 1];
                *(float2*)(yp + nt * 8) = o;
            }
        }
    }
}

// ---------------- combine ----------------
__global__ void combine_kernel(float* __restrict__ out) {
    const int idx = blockIdx.x * blockDim.x + threadIdx.x;
    const int t = idx / (HD / 4);
    const int c4 = idx % (HD / 4);
    float4 acc = make_float4(0.f, 0.f, 0.f, 0.f);
    #pragma unroll
    for (int k = 0; k < TOPK; k++) {
        int e = g_sel_e[t * 2 + k];
        int s = g_sel_s[t * 2 + k];
        float w = g_sel_w[t * 2 + k];
        const float4 v = *(const float4*)(g_y + (size_t)(g_base[e] + s) * HD + c4 * 4);
        acc.x += w * v.x; acc.y += w * v.y; acc.z += w * v.z; acc.w += w * v.w;
    }
    *(float4*)(out + (size_t)t * HD + c4 * 4) = acc;
}

// ---------------- launcher ----------------
extern "C" void kernel_launch(void* const* d_in, const int* in_sizes, int n_in,
                              void* d_out, int out_size) {
    const float* x  = (const float*)d_in[0];
    const float* Wg = (const float*)d_in[1];
    const float* bg = (const float*)d_in[2];
    const float* W1 = (const float*)d_in[3];
    const float* W3 = (const float*)d_in[4];
    const float* W2 = (const float*)d_in[5];
    float* out = (float*)d_out;

    zero_counts_kernel<<<1, 32>>>();
    routing_kernel<<<TOK, 256>>>(x, Wg, bg);
    bases_kernel<<<1, 1>>>();
    gemm1_mma<<<dim3(FF / 64, TOK / 128, NE), 256>>>(x, W1, W3);
    gemm2_mma<<<dim3(HD / 128, TOK / 128, NE), 256>>>(W2);
    combine_kernel<<<(TOK * (HD / 4)) / 256, 256>>>(out);
}

// round 4
// speedup vs baseline: 2.9501x; 2.2818x over previous
#include <cuda_runtime.h>
#include <cstdint>

#define TOK 4096   // B*S tokens
#define HD  1024
#define NE  8
#define FF  4096
#define TOPK 2

// ---------------- scratch (device globals) ----------------
__device__ int   g_counts[NE];
__device__ int   g_base[NE];
__device__ int   g_tok[NE][TOK];
__device__ int   g_sel_e[TOK * TOPK];
__device__ int   g_sel_s[TOK * TOPK];
__device__ float g_sel_w[TOK * TOPK];
__device__ float g_h[(size_t)TOK * TOPK * FF];   // pre-rounded tf32 bits (written by gemm1)
__device__ float g_y[(size_t)TOK * TOPK * HD];
// tf32-rounded copies of operands
__device__ float g_xt[(size_t)TOK * HD];
__device__ float g_w1t[(size_t)NE * HD * FF];
__device__ float g_w3t[(size_t)NE * HD * FF];
__device__ float g_w2t[(size_t)NE * FF * HD];

// ---------------- helpers ----------------
__device__ __forceinline__ uint32_t f2tf(float f) {
    uint32_t u; asm("cvt.rna.tf32.f32 %0, %1;" : "=r"(u) : "f"(f)); return u;
}
__device__ __forceinline__ uint32_t smem_u32(const void* p) {
    uint32_t a;
    asm("{ .reg .u64 t; cvta.to.shared.u64 t, %1; cvt.u32.u64 %0, t; }" : "=r"(a) : "l"(p));
    return a;
}
__device__ __forceinline__ void mma8(float* d, const uint32_t* a, const uint32_t* b) {
    asm volatile("mma.sync.aligned.m16n8k8.row.col.f32.tf32.tf32.f32 "
        "{%0,%1,%2,%3}, {%4,%5,%6,%7}, {%8,%9}, {%0,%1,%2,%3};"
        : "+f"(d[0]), "+f"(d[1]), "+f"(d[2]), "+f"(d[3])
        : "r"(a[0]), "r"(a[1]), "r"(a[2]), "r"(a[3]), "r"(b[0]), "r"(b[1]));
}
#define CP16(dst32, src) \
    asm volatile("cp.async.cg.shared.global [%0], [%1], 16;" :: "r"(dst32), "l"(src) : "memory")
#define CP_COMMIT() asm volatile("cp.async.commit_group;" ::: "memory")
#define CP_WAIT0()  asm volatile("cp.async.wait_group 0;" ::: "memory")
#define CP_WAIT1()  asm volatile("cp.async.wait_group 1;" ::: "memory")

// ---------------- prep: tf32-round a buffer ----------------
__global__ void round_tf32_kernel(const float4* __restrict__ src,
                                  float4* __restrict__ dst, int n4) {
    int i = blockIdx.x * blockDim.x + threadIdx.x;
    if (i < n4) {
        float4 v = src[i];
        float4 o;
        o.x = __uint_as_float(f2tf(v.x));
        o.y = __uint_as_float(f2tf(v.y));
        o.z = __uint_as_float(f2tf(v.z));
        o.w = __uint_as_float(f2tf(v.w));
        dst[i] = o;
    }
}

// ---------------- kernel 0: zero counters ----------------
__global__ void zero_counts_kernel() {
    if (threadIdx.x < NE) g_counts[threadIdx.x] = 0;
}

// ---------------- kernel 1: routing ----------------
__global__ void routing_kernel(const float* __restrict__ x,
                               const float* __restrict__ Wg,
                               const float* __restrict__ bg) {
    const int t = blockIdx.x, tid = threadIdx.x, wid = tid >> 5, lid = tid & 31;
    __shared__ float s_logit[NE];
    const float* xt = x + (size_t)t * HD;
    float acc = 0.f;
    for (int h = lid; h < HD; h += 32) acc += xt[h] * Wg[h * NE + wid];
    #pragma unroll
    for (int o = 16; o > 0; o >>= 1) acc += __shfl_down_sync(0xFFFFFFFFu, acc, o);
    if (lid == 0) s_logit[wid] = acc + bg[wid];
    __syncthreads();
    if (tid == 0) {
        float l[NE];
        #pragma unroll
        for (int e = 0; e < NE; e++) l[e] = s_logit[e];
        int i0 = 0;
        #pragma unroll
        for (int e = 1; e < NE; e++) if (l[e] > l[i0]) i0 = e;
        int i1 = (i0 == 0) ? 1 : 0;
        #pragma unroll
        for (int e = 0; e < NE; e++) if (e != i0 && l[e] > l[i1]) i1 = e;
        float w1 = __expf(l[i1] - l[i0]);
        float inv = 1.f / (1.f + w1);
        int s0 = atomicAdd(&g_counts[i0], 1);
        int s1 = atomicAdd(&g_counts[i1], 1);
        g_tok[i0][s0] = t;  g_tok[i1][s1] = t;
        g_sel_e[t*2+0] = i0; g_sel_s[t*2+0] = s0; g_sel_w[t*2+0] = inv;
        g_sel_e[t*2+1] = i1; g_sel_s[t*2+1] = s1; g_sel_w[t*2+1] = w1 * inv;
    }
}

// ---------------- kernel 2: bases ----------------
__global__ void bases_kernel() {
    if (threadIdx.x == 0) {
        int b = 0;
        #pragma unroll
        for (int e = 0; e < NE; e++) { g_base[e] = b; b += g_counts[e]; }
    }
}

// ======================= GEMM1 =======================
// CTA 128M x 64N fused (W1,W3), BK=32, 2-stage cp.async pipeline, 2 CTA/SM.
// smem: toks[128] @0 | A[2][128][36] @512 | B1[2][32][68] @37376 | B3[2][32][68] @54784
#define G1_SMEM 72192
#define G1_A_OFF 512
#define G1_B1_OFF 37376
#define G1_B3_OFF 54784

__global__ __launch_bounds__(256, 2) void gemm1_mma(const float* __restrict__ dummy) {
    const int e  = blockIdx.z;
    const int n  = g_counts[e];
    const int m0 = blockIdx.y * 128;
    if (m0 >= n) return;
    const int n0   = blockIdx.x * 64;
    const int base = g_base[e];

    extern __shared__ char dynsmem[];
    const uint32_t sb = smem_u32(dynsmem);
    int* toks = (int*)dynsmem;
    const uint32_t* As  = (const uint32_t*)(dynsmem + G1_A_OFF);
    const uint32_t* B1s = (const uint32_t*)(dynsmem + G1_B1_OFF);
    const uint32_t* B3s = (const uint32_t*)(dynsmem + G1_B3_OFF);

    const int tid = threadIdx.x, wid = tid >> 5, lane = tid & 31;
    const int g = lane >> 2, tig = lane & 3;
    const int wm = wid >> 1, wn = wid & 1;

    if (tid < 128) { int r = m0 + tid; toks[tid] = g_tok[e][r < n ? r : n - 1]; }
    __syncthreads();

    const float* __restrict__ W1t = g_w1t + (size_t)e * HD * FF;
    const float* __restrict__ W3t = g_w3t + (size_t)e * HD * FF;

    float cg[2][4][4] = {};
    float cu[2][4][4] = {};

    // --- issue stage 0 ---
    {
        const int k0 = 0, s = 0;
        const uint32_t aB = sb + G1_A_OFF + s * 18432;
        #pragma unroll
        for (int q = 0; q < 4; q++) {
            int id = q * 256 + tid, row = id >> 3, c4 = id & 7;
            CP16(aB + row * 144 + c4 * 16, g_xt + (size_t)toks[row] * HD + k0 + c4 * 4);
        }
        const uint32_t b1B = sb + G1_B1_OFF + s * 8704;
        const uint32_t b3B = sb + G1_B3_OFF + s * 8704;
        #pragma unroll
        for (int q = 0; q < 2; q++) {
            int id = q * 256 + tid, kl = id >> 4, nq = id & 15;
            size_t off = (size_t)(k0 + kl) * FF + n0 + nq * 4;
            CP16(b1B + kl * 272 + nq * 16, W1t + off);
            CP16(b3B + kl * 272 + nq * 16, W3t + off);
        }
        CP_COMMIT();
    }

    const int NC = HD / 32;
    for (int c = 0; c < NC; c++) {
        if (c + 1 < NC) {
            const int k0 = (c + 1) * 32, s = (c + 1) & 1;
            const uint32_t aB = sb + G1_A_OFF + s * 18432;
            #pragma unroll
            for (int q = 0; q < 4; q++) {
                int id = q * 256 + tid, row = id >> 3, c4 = id & 7;
                CP16(aB + row * 144 + c4 * 16, g_xt + (size_t)toks[row] * HD + k0 + c4 * 4);
            }
            const uint32_t b1B = sb + G1_B1_OFF + s * 8704;
            const uint32_t b3B = sb + G1_B3_OFF + s * 8704;
            #pragma unroll
            for (int q = 0; q < 2; q++) {
                int id = q * 256 + tid, kl = id >> 4, nq = id & 15;
                size_t off = (size_t)(k0 + kl) * FF + n0 + nq * 4;
                CP16(b1B + kl * 272 + nq * 16, W1t + off);
                CP16(b3B + kl * 272 + nq * 16, W3t + off);
            }
            CP_COMMIT();
            CP_WAIT1();
        } else {
            CP_WAIT0();
        }
        __syncthreads();

        const uint32_t* Ap  = As  + (c & 1) * 4608;   // 128*36
        const uint32_t* B1p = B1s + (c & 1) * 2176;   // 32*68
        const uint32_t* B3p = B3s + (c & 1) * 2176;

        #pragma unroll
        for (int ks = 0; ks < 4; ks++) {
            const int kk = ks * 8;
            uint32_t a[2][4];
            #pragma unroll
            for (int mt = 0; mt < 2; mt++) {
                const int rb = wm * 32 + mt * 16;
                a[mt][0] = Ap[(rb + g) * 36 + kk + tig];
                a[mt][1] = Ap[(rb + g + 8) * 36 + kk + tig];
                a[mt][2] = Ap[(rb + g) * 36 + kk + tig + 4];
                a[mt][3] = Ap[(rb + g + 8) * 36 + kk + tig + 4];
            }
            #pragma unroll
            for (int nt = 0; nt < 4; nt++) {
                const int nb = wn * 32 + nt * 8;
                uint32_t b1[2] = { B1p[(kk + tig) * 68 + nb + g], B1p[(kk + tig + 4) * 68 + nb + g] };
                uint32_t b3[2] = { B3p[(kk + tig) * 68 + nb + g], B3p[(kk + tig + 4) * 68 + nb + g] };
                #pragma unroll
                for (int mt = 0; mt < 2; mt++) {
                    mma8(cg[mt][nt], a[mt], b1);
                    mma8(cu[mt][nt], a[mt], b3);
                }
            }
        }
        __syncthreads();
    }

    // epilogue: h = silu(g) * u, pre-rounded to tf32 for gemm2
    #pragma unroll
    for (int mt = 0; mt < 2; mt++) {
        #pragma unroll
        for (int half = 0; half < 2; half++) {
            const int r = m0 + wm * 32 + mt * 16 + g + half * 8;
            if (r >= n) continue;
            float* hp = g_h + (size_t)(base + r) * FF + n0 + wn * 32 + 2 * tig;
            #pragma unroll
            for (int nt = 0; nt < 4; nt++) {
                float g0 = cg[mt][nt][half * 2 + 0], g1 = cg[mt][nt][half * 2 + 1];
                float u0 = cu[mt][nt][half * 2 + 0], u1 = cu[mt][nt][half * 2 + 1];
                float2 o;
                o.x = __uint_as_float(f2tf((g0 / (1.f + __expf(-g0))) * u0));
                o.y = __uint_as_float(f2tf((g1 / (1.f + __expf(-g1))) * u1));
                *(float2*)(hp + nt * 8) = o;
            }
        }
    }
}

// ======================= GEMM2 =======================
// CTA 128M x 128N, BK=32, 2-stage cp.async, 2 CTA/SM.
// smem: A[2][128][36] @0 | B[2][32][132] @36864
#define G2_SMEM 70656
#define G2_B_OFF 36864

__global__ __launch_bounds__(256, 2) void gemm2_mma(const float* __restrict__ dummy) {
    const int e  = blockIdx.z;
    const int n  = g_counts[e];
    const int m0 = blockIdx.y * 128;
    if (m0 >= n) return;
    const int n0   = blockIdx.x * 128;
    const int base = g_base[e];

    extern __shared__ char dynsmem[];
    const uint32_t sb = smem_u32(dynsmem);
    const uint32_t* As = (const uint32_t*)dynsmem;
    const uint32_t* Bs = (const uint32_t*)(dynsmem + G2_B_OFF);

    const int tid = threadIdx.x, wid = tid >> 5, lane = tid & 31;
    const int g = lane >> 2, tig = lane & 3;
    const int wm = wid >> 1, wn = wid & 1;

    const float* __restrict__ W2t = g_w2t + (size_t)e * FF * HD;

    float cacc[2][8][4] = {};

    // --- issue stage 0 ---
    {
        const int k0 = 0, s = 0;
        const uint32_t aB = sb + s * 18432;
        #pragma unroll
        for (int q = 0; q < 4; q++) {
            int id = q * 256 + tid, row = id >> 3, c4 = id & 7;
            int rg = m0 + row; if (rg >= n) rg = n - 1;
            CP16(aB + row * 144 + c4 * 16, g_h + (size_t)(base + rg) * FF + k0 + c4 * 4);
        }
        const uint32_t bB = sb + G2_B_OFF + s * 16896;
        #pragma unroll
        for (int q = 0; q < 4; q++) {
            int id = q * 256 + tid, kl = id >> 5, nq = id & 31;
            CP16(bB + kl * 528 + nq * 16, W2t + (size_t)(k0 + kl) * HD + n0 + nq * 4);
        }
        CP_COMMIT();
    }

    const int NC = FF / 32;
    for (int c = 0; c < NC; c++) {
        if (c + 1 < NC) {
            const int k0 = (c + 1) * 32, s = (c + 1) & 1;
            const uint32_t aB = sb + s * 18432;
            #pragma unroll
            for (int q = 0; q < 4; q++) {
                int id = q * 256 + tid, row = id >> 3, c4 = id & 7;
                int rg = m0 + row; if (rg >= n) rg = n - 1;
                CP16(aB + row * 144 + c4 * 16, g_h + (size_t)(base + rg) * FF + k0 + c4 * 4);
            }
            const uint32_t bB = sb + G2_B_OFF + s * 16896;
            #pragma unroll
            for (int q = 0; q < 4; q++) {
                int id = q * 256 + tid, kl = id >> 5, nq = id & 31;
                CP16(bB + kl * 528 + nq * 16, W2t + (size_t)(k0 + kl) * HD + n0 + nq * 4);
            }
            CP_COMMIT();
            CP_WAIT1();
        } else {
            CP_WAIT0();
        }
        __syncthreads();

        const uint32_t* Ap = As + (c & 1) * 4608;   // 128*36
        const uint32_t* Bp = Bs + (c & 1) * 4224;   // 32*132

        #pragma unroll
        for (int ks = 0; ks < 4; ks++) {
            const int kk = ks * 8;
            uint32_t a[2][4];
            #pragma unroll
            for (int mt = 0; mt < 2; mt++) {
                const int rb = wm * 32 + mt * 16;
                a[mt][0] = Ap[(rb + g) * 36 + kk + tig];
                a[mt][1] = Ap[(rb + g + 8) * 36 + kk + tig];
                a[mt][2] = Ap[(rb + g) * 36 + kk + tig + 4];
                a[mt][3] = Ap[(rb + g + 8) * 36 + kk + tig + 4];
            }
            #pragma unroll
            for (int nt = 0; nt < 8; nt++) {
                const int nb = wn * 64 + nt * 8;
                uint32_t b[2] = { Bp[(kk + tig) * 132 + nb + g], Bp[(kk + tig + 4) * 132 + nb + g] };
                #pragma unroll
                for (int mt = 0; mt < 2; mt++) mma8(cacc[mt][nt], a[mt], b);
            }
        }
        __syncthreads();
    }

    #pragma unroll
    for (int mt = 0; mt < 2; mt++) {
        #pragma unroll
        for (int half = 0; half < 2; half++) {
            const int r = m0 + wm * 32 + mt * 16 + g + half * 8;
            if (r >= n) continue;
            float* yp = g_y + (size_t)(base + r) * HD + n0 + wn * 64 + 2 * tig;
            #pragma unroll
            for (int nt = 0; nt < 8; nt++) {
                float2 o;
                o.x = cacc[mt][nt][half * 2 + 0];
                o.y = cacc[mt][nt][half * 2 + 1];
                *(float2*)(yp + nt * 8) = o;
            }
        }
    }
}

// ---------------- combine ----------------
__global__ void combine_kernel(float* __restrict__ out) {
    const int idx = blockIdx.x * blockDim.x + threadIdx.x;
    const int t = idx / (HD / 4);
    const int c4 = idx % (HD / 4);
    float4 acc = make_float4(0.f, 0.f, 0.f, 0.f);
    #pragma unroll
    for (int k = 0; k < TOPK; k++) {
        int e = g_sel_e[t * 2 + k];
        int s = g_sel_s[t * 2 + k];
        float w = g_sel_w[t * 2 + k];
        const float4 v = *(const float4*)(g_y + (size_t)(g_base[e] + s) * HD + c4 * 4);
        acc.x += w * v.x; acc.y += w * v.y; acc.z += w * v.z; acc.w += w * v.w;
    }
    *(float4*)(out + (size_t)t * HD + c4 * 4) = acc;
}

// ---------------- launcher ----------------
extern "C" void kernel_launch(void* const* d_in, const int* in_sizes, int n_in,
                              void* d_out, int out_size) {
    const float* x  = (const float*)d_in[0];
    const float* Wg = (const float*)d_in[1];
    const float* bg = (const float*)d_in[2];
    const float* W1 = (const float*)d_in[3];
    const float* W3 = (const float*)d_in[4];
    const float* W2 = (const float*)d_in[5];
    float* out = (float*)d_out;

    static int attr_done = 0;
    cudaFuncSetAttribute(gemm1_mma, cudaFuncAttributeMaxDynamicSharedMemorySize, G1_SMEM);
    cudaFuncSetAttribute(gemm2_mma, cudaFuncAttributeMaxDynamicSharedMemorySize, G2_SMEM);
    (void)attr_done;

    // resolve device-global addresses
    float *xt_p, *w1t_p, *w3t_p, *w2t_p;
    cudaGetSymbolAddress((void**)&xt_p,  g_xt);
    cudaGetSymbolAddress((void**)&w1t_p, g_w1t);
    cudaGetSymbolAddress((void**)&w3t_p, g_w3t);
    cudaGetSymbolAddress((void**)&w2t_p, g_w2t);

    const int wN4 = NE * HD * FF / 4;   // 8.39M float4
    const int xN4 = TOK * HD / 4;       // 1.05M float4

    round_tf32_kernel<<<(xN4 + 255) / 256, 256>>>((const float4*)x,  (float4*)xt_p,  xN4);
    round_tf32_kernel<<<(wN4 + 255) / 256, 256>>>((const float4*)W1, (float4*)w1t_p, wN4);
    round_tf32_kernel<<<(wN4 + 255) / 256, 256>>>((const float4*)W3, (float4*)w3t_p, wN4);
    round_tf32_kernel<<<(wN4 + 255) / 256, 256>>>((const float4*)W2, (float4*)w2t_p, wN4);

    zero_counts_kernel<<<1, 32>>>();
    routing_kernel<<<TOK, 256>>>(x, Wg, bg);
    bases_kernel<<<1, 1>>>();
    gemm1_mma<<<dim3(FF / 64, TOK / 128, NE), 256, G1_SMEM>>>(x);
    gemm2_mma<<<dim3(HD / 128, TOK / 128, NE), 256, G2_SMEM>>>(x);
    combine_kernel<<<(TOK * (HD / 4)) / 256, 256>>>(out);
}

// round 5
// speedup vs baseline: 3.3078x; 1.1213x over previous
#include <cuda_runtime.h>
#include <cstdint>

#define TOK 4096   // B*S tokens
#define HD  1024
#define NE  8
#define FF  4096
#define TOPK 2

// ---------------- scratch (device globals) ----------------
__device__ int   g_counts[NE];
__device__ int   g_base[NE];
__device__ int   g_tok[NE][TOK];
__device__ int   g_sel_e[TOK * TOPK];
__device__ int   g_sel_s[TOK * TOPK];
__device__ float g_sel_w[TOK * TOPK];
__device__ float g_h[(size_t)TOK * TOPK * FF];   // pre-rounded tf32 bits (written by gemm1)
__device__ float g_y[(size_t)TOK * TOPK * HD];
// tf32-rounded copies of operands
__device__ float g_xt[(size_t)TOK * HD];
__device__ float g_w1t[(size_t)NE * HD * FF];
__device__ float g_w3t[(size_t)NE * HD * FF];
__device__ float g_w2t[(size_t)NE * FF * HD];

// ---------------- helpers ----------------
__device__ __forceinline__ uint32_t f2tf(float f) {
    uint32_t u; asm("cvt.rna.tf32.f32 %0, %1;" : "=r"(u) : "f"(f)); return u;
}
__device__ __forceinline__ uint32_t smem_u32(const void* p) {
    uint32_t a;
    asm("{ .reg .u64 t; cvta.to.shared.u64 t, %1; cvt.u32.u64 %0, t; }" : "=r"(a) : "l"(p));
    return a;
}
__device__ __forceinline__ void mma8(float* d, const uint32_t* a, const uint32_t* b) {
    asm volatile("mma.sync.aligned.m16n8k8.row.col.f32.tf32.tf32.f32 "
        "{%0,%1,%2,%3}, {%4,%5,%6,%7}, {%8,%9}, {%0,%1,%2,%3};"
        : "+f"(d[0]), "+f"(d[1]), "+f"(d[2]), "+f"(d[3])
        : "r"(a[0]), "r"(a[1]), "r"(a[2]), "r"(a[3]), "r"(b[0]), "r"(b[1]));
}
#define CP16(dst32, src) \
    asm volatile("cp.async.cg.shared.global [%0], [%1], 16;" :: "r"(dst32), "l"(src) : "memory")
#define CP_COMMIT() asm volatile("cp.async.commit_group;" ::: "memory")
#define CP_WAIT0()  asm volatile("cp.async.wait_group 0;" ::: "memory")
#define CP_WAIT1()  asm volatile("cp.async.wait_group 1;" ::: "memory")

// ---------------- prep: tf32-round a buffer ----------------
__global__ void round_tf32_kernel(const float4* __restrict__ src,
                                  float4* __restrict__ dst, int n4) {
    int i = blockIdx.x * blockDim.x + threadIdx.x;
    if (i < n4) {
        float4 v = src[i];
        float4 o;
        o.x = __uint_as_float(f2tf(v.x));
        o.y = __uint_as_float(f2tf(v.y));
        o.z = __uint_as_float(f2tf(v.z));
        o.w = __uint_as_float(f2tf(v.w));
        dst[i] = o;
    }
}

// ---------------- kernel 0: zero counters ----------------
__global__ void zero_counts_kernel() {
    if (threadIdx.x < NE) g_counts[threadIdx.x] = 0;
}

// ---------------- kernel 1: routing ----------------
__global__ void routing_kernel(const float* __restrict__ x,
                               const float* __restrict__ Wg,
                               const float* __restrict__ bg) {
    const int t = blockIdx.x, tid = threadIdx.x, wid = tid >> 5, lid = tid & 31;
    __shared__ float s_logit[NE];
    const float* xt = x + (size_t)t * HD;
    float acc = 0.f;
    for (int h = lid; h < HD; h += 32) acc += xt[h] * Wg[h * NE + wid];
    #pragma unroll
    for (int o = 16; o > 0; o >>= 1) acc += __shfl_down_sync(0xFFFFFFFFu, acc, o);
    if (lid == 0) s_logit[wid] = acc + bg[wid];
    __syncthreads();
    if (tid == 0) {
        float l[NE];
        #pragma unroll
        for (int e = 0; e < NE; e++) l[e] = s_logit[e];
        int i0 = 0;
        #pragma unroll
        for (int e = 1; e < NE; e++) if (l[e] > l[i0]) i0 = e;
        int i1 = (i0 == 0) ? 1 : 0;
        #pragma unroll
        for (int e = 0; e < NE; e++) if (e != i0 && l[e] > l[i1]) i1 = e;
        float w1 = __expf(l[i1] - l[i0]);
        float inv = 1.f / (1.f + w1);
        int s0 = atomicAdd(&g_counts[i0], 1);
        int s1 = atomicAdd(&g_counts[i1], 1);
        g_tok[i0][s0] = t;  g_tok[i1][s1] = t;
        g_sel_e[t*2+0] = i0; g_sel_s[t*2+0] = s0; g_sel_w[t*2+0] = inv;
        g_sel_e[t*2+1] = i1; g_sel_s[t*2+1] = s1; g_sel_w[t*2+1] = w1 * inv;
    }
}

// ---------------- kernel 2: bases ----------------
__global__ void bases_kernel() {
    if (threadIdx.x == 0) {
        int b = 0;
        #pragma unroll
        for (int e = 0; e < NE; e++) { g_base[e] = b; b += g_counts[e]; }
    }
}

// ======================= GEMM1 =======================
// CTA 128M x 64N fused (W1,W3), BK=32, 2-stage cp.async pipeline, 2 CTA/SM.
// Bank-conflict-free pads: A row = 36 words (bank 4g+tig), B row = 72 words (bank 8tig+g).
// smem: toks[128] @0 | A[2][128][36] @512 | B1[2][32][72] @37376 | B3[2][32][72] @55808
#define G1_A_OFF  512
#define G1_B1_OFF 37376
#define G1_B3_OFF 55808
#define G1_SMEM   74240

__global__ __launch_bounds__(256, 2) void gemm1_mma() {
    const int e  = blockIdx.z;
    const int n  = g_counts[e];
    const int m0 = blockIdx.y * 128;
    if (m0 >= n) return;
    const int n0   = blockIdx.x * 64;
    const int base = g_base[e];

    extern __shared__ char dynsmem[];
    const uint32_t sb = smem_u32(dynsmem);
    int* toks = (int*)dynsmem;
    const uint32_t* As  = (const uint32_t*)(dynsmem + G1_A_OFF);
    const uint32_t* B1s = (const uint32_t*)(dynsmem + G1_B1_OFF);
    const uint32_t* B3s = (const uint32_t*)(dynsmem + G1_B3_OFF);

    const int tid = threadIdx.x, wid = tid >> 5, lane = tid & 31;
    const int g = lane >> 2, tig = lane & 3;
    const int wm = wid >> 1, wn = wid & 1;

    if (tid < 128) { int r = m0 + tid; toks[tid] = g_tok[e][r < n ? r : n - 1]; }
    __syncthreads();

    const float* __restrict__ W1t = g_w1t + (size_t)e * HD * FF;
    const float* __restrict__ W3t = g_w3t + (size_t)e * HD * FF;

    float cg[2][4][4] = {};
    float cu[2][4][4] = {};

    // --- issue stage 0 ---
    {
        const int k0 = 0;
        const uint32_t aB = sb + G1_A_OFF;
        #pragma unroll
        for (int q = 0; q < 4; q++) {
            int id = q * 256 + tid, row = id >> 3, c4 = id & 7;
            CP16(aB + row * 144 + c4 * 16, g_xt + (size_t)toks[row] * HD + k0 + c4 * 4);
        }
        const uint32_t b1B = sb + G1_B1_OFF;
        const uint32_t b3B = sb + G1_B3_OFF;
        #pragma unroll
        for (int q = 0; q < 2; q++) {
            int id = q * 256 + tid, kl = id >> 4, nq = id & 15;
            size_t off = (size_t)(k0 + kl) * FF + n0 + nq * 4;
            CP16(b1B + kl * 288 + nq * 16, W1t + off);
            CP16(b3B + kl * 288 + nq * 16, W3t + off);
        }
        CP_COMMIT();
    }

    const int NC = HD / 32;
    for (int c = 0; c < NC; c++) {
        if (c + 1 < NC) {
            const int k0 = (c + 1) * 32, s = (c + 1) & 1;
            const uint32_t aB = sb + G1_A_OFF + s * 18432;
            #pragma unroll
            for (int q = 0; q < 4; q++) {
                int id = q * 256 + tid, row = id >> 3, c4 = id & 7;
                CP16(aB + row * 144 + c4 * 16, g_xt + (size_t)toks[row] * HD + k0 + c4 * 4);
            }
            const uint32_t b1B = sb + G1_B1_OFF + s * 9216;
            const uint32_t b3B = sb + G1_B3_OFF + s * 9216;
            #pragma unroll
            for (int q = 0; q < 2; q++) {
                int id = q * 256 + tid, kl = id >> 4, nq = id & 15;
                size_t off = (size_t)(k0 + kl) * FF + n0 + nq * 4;
                CP16(b1B + kl * 288 + nq * 16, W1t + off);
                CP16(b3B + kl * 288 + nq * 16, W3t + off);
            }
            CP_COMMIT();
            CP_WAIT1();
        } else {
            CP_WAIT0();
        }
        __syncthreads();

        const uint32_t* Ap  = As  + (c & 1) * 4608;   // 128*36
        const uint32_t* B1p = B1s + (c & 1) * 2304;   // 32*72
        const uint32_t* B3p = B3s + (c & 1) * 2304;

        #pragma unroll
        for (int ks = 0; ks < 4; ks++) {
            const int kk = ks * 8;
            uint32_t a[2][4];
            #pragma unroll
            for (int mt = 0; mt < 2; mt++) {
                const int rb = wm * 32 + mt * 16;
                a[mt][0] = Ap[(rb + g) * 36 + kk + tig];
                a[mt][1] = Ap[(rb + g + 8) * 36 + kk + tig];
                a[mt][2] = Ap[(rb + g) * 36 + kk + tig + 4];
                a[mt][3] = Ap[(rb + g + 8) * 36 + kk + tig + 4];
            }
            #pragma unroll
            for (int nt = 0; nt < 4; nt++) {
                const int nb = wn * 32 + nt * 8;
                uint32_t b1[2] = { B1p[(kk + tig) * 72 + nb + g], B1p[(kk + tig + 4) * 72 + nb + g] };
                uint32_t b3[2] = { B3p[(kk + tig) * 72 + nb + g], B3p[(kk + tig + 4) * 72 + nb + g] };
                #pragma unroll
                for (int mt = 0; mt < 2; mt++) {
                    mma8(cg[mt][nt], a[mt], b1);
                    mma8(cu[mt][nt], a[mt], b3);
                }
            }
        }
        __syncthreads();
    }

    // epilogue: h = silu(g) * u, pre-rounded to tf32 for gemm2
    #pragma unroll
    for (int mt = 0; mt < 2; mt++) {
        #pragma unroll
        for (int half = 0; half < 2; half++) {
            const int r = m0 + wm * 32 + mt * 16 + g + half * 8;
            if (r >= n) continue;
            float* hp = g_h + (size_t)(base + r) * FF + n0 + wn * 32 + 2 * tig;
            #pragma unroll
            for (int nt = 0; nt < 4; nt++) {
                float g0 = cg[mt][nt][half * 2 + 0], g1 = cg[mt][nt][half * 2 + 1];
                float u0 = cu[mt][nt][half * 2 + 0], u1 = cu[mt][nt][half * 2 + 1];
                float2 o;
                o.x = __uint_as_float(f2tf((g0 / (1.f + __expf(-g0))) * u0));
                o.y = __uint_as_float(f2tf((g1 / (1.f + __expf(-g1))) * u1));
                *(float2*)(hp + nt * 8) = o;
            }
        }
    }
}

// ======================= GEMM2 =======================
// CTA 128M x 128N, BK=32, 2-stage cp.async, 2 CTA/SM.
// Pads: A 36 words, B 136 words (bank 8tig+g — conflict-free).
// smem: A[2][128][36] @0 | B[2][32][136] @36864
#define G2_B_OFF 36864
#define G2_SMEM  71680

__global__ __launch_bounds__(256, 2) void gemm2_mma() {
    const int e  = blockIdx.z;
    const int n  = g_counts[e];
    const int m0 = blockIdx.y * 128;
    if (m0 >= n) return;
    const int n0   = blockIdx.x * 128;
    const int base = g_base[e];

    extern __shared__ char dynsmem[];
    const uint32_t sb = smem_u32(dynsmem);
    const uint32_t* As = (const uint32_t*)dynsmem;
    const uint32_t* Bs = (const uint32_t*)(dynsmem + G2_B_OFF);

    const int tid = threadIdx.x, wid = tid >> 5, lane = tid & 31;
    const int g = lane >> 2, tig = lane & 3;
    const int wm = wid >> 1, wn = wid & 1;

    const float* __restrict__ W2t = g_w2t + (size_t)e * FF * HD;

    float cacc[2][8][4] = {};

    // --- issue stage 0 ---
    {
        const int k0 = 0;
        const uint32_t aB = sb;
        #pragma unroll
        for (int q = 0; q < 4; q++) {
            int id = q * 256 + tid, row = id >> 3, c4 = id & 7;
            int rg = m0 + row; if (rg >= n) rg = n - 1;
            CP16(aB + row * 144 + c4 * 16, g_h + (size_t)(base + rg) * FF + k0 + c4 * 4);
        }
        const uint32_t bB = sb + G2_B_OFF;
        #pragma unroll
        for (int q = 0; q < 4; q++) {
            int id = q * 256 + tid, kl = id >> 5, nq = id & 31;
            CP16(bB + kl * 544 + nq * 16, W2t + (size_t)(k0 + kl) * HD + n0 + nq * 4);
        }
        CP_COMMIT();
    }

    const int NC = FF / 32;
    for (int c = 0; c < NC; c++) {
        if (c + 1 < NC) {
            const int k0 = (c + 1) * 32, s = (c + 1) & 1;
            const uint32_t aB = sb + s * 18432;
            #pragma unroll
            for (int q = 0; q < 4; q++) {
                int id = q * 256 + tid, row = id >> 3, c4 = id & 7;
                int rg = m0 + row; if (rg >= n) rg = n - 1;
                CP16(aB + row * 144 + c4 * 16, g_h + (size_t)(base + rg) * FF + k0 + c4 * 4);
            }
            const uint32_t bB = sb + G2_B_OFF + s * 17408;
            #pragma unroll
            for (int q = 0; q < 4; q++) {
                int id = q * 256 + tid, kl = id >> 5, nq = id & 31;
                CP16(bB + kl * 544 + nq * 16, W2t + (size_t)(k0 + kl) * HD + n0 + nq * 4);
            }
            CP_COMMIT();
            CP_WAIT1();
        } else {
            CP_WAIT0();
        }
        __syncthreads();

        const uint32_t* Ap = As + (c & 1) * 4608;   // 128*36
        const uint32_t* Bp = Bs + (c & 1) * 4352;   // 32*136

        #pragma unroll
        for (int ks = 0; ks < 4; ks++) {
            const int kk = ks * 8;
            uint32_t a[2][4];
            #pragma unroll
            for (int mt = 0; mt < 2; mt++) {
                const int rb = wm * 32 + mt * 16;
                a[mt][0] = Ap[(rb + g) * 36 + kk + tig];
                a[mt][1] = Ap[(rb + g + 8) * 36 + kk + tig];
                a[mt][2] = Ap[(rb + g) * 36 + kk + tig + 4];
                a[mt][3] = Ap[(rb + g + 8) * 36 + kk + tig + 4];
            }
            #pragma unroll
            for (int nt = 0; nt < 8; nt++) {
                const int nb = wn * 64 + nt * 8;
                uint32_t b[2] = { Bp[(kk + tig) * 136 + nb + g], Bp[(kk + tig + 4) * 136 + nb + g] };
                #pragma unroll
                for (int mt = 0; mt < 2; mt++) mma8(cacc[mt][nt], a[mt], b);
            }
        }
        __syncthreads();
    }

    #pragma unroll
    for (int mt = 0; mt < 2; mt++) {
        #pragma unroll
        for (int half = 0; half < 2; half++) {
            const int r = m0 + wm * 32 + mt * 16 + g + half * 8;
            if (r >= n) continue;
            float* yp = g_y + (size_t)(base + r) * HD + n0 + wn * 64 + 2 * tig;
            #pragma unroll
            for (int nt = 0; nt < 8; nt++) {
                float2 o;
                o.x = cacc[mt][nt][half * 2 + 0];
                o.y = cacc[mt][nt][half * 2 + 1];
                *(float2*)(yp + nt * 8) = o;
            }
        }
    }
}

// ---------------- combine ----------------
__global__ void combine_kernel(float* __restrict__ out) {
    const int idx = blockIdx.x * blockDim.x + threadIdx.x;
    const int t = idx / (HD / 4);
    const int c4 = idx % (HD / 4);
    float4 acc = make_float4(0.f, 0.f, 0.f, 0.f);
    #pragma unroll
    for (int k = 0; k < TOPK; k++) {
        int e = g_sel_e[t * 2 + k];
        int s = g_sel_s[t * 2 + k];
        float w = g_sel_w[t * 2 + k];
        const float4 v = *(const float4*)(g_y + (size_t)(g_base[e] + s) * HD + c4 * 4);
        acc.x += w * v.x; acc.y += w * v.y; acc.z += w * v.z; acc.w += w * v.w;
    }
    *(float4*)(out + (size_t)t * HD + c4 * 4) = acc;
}

// ---------------- launcher ----------------
extern "C" void kernel_launch(void* const* d_in, const int* in_sizes, int n_in,
                              void* d_out, int out_size) {
    const float* x  = (const float*)d_in[0];
    const float* Wg = (const float*)d_in[1];
    const float* bg = (const float*)d_in[2];
    const float* W1 = (const float*)d_in[3];
    const float* W3 = (const float*)d_in[4];
    const float* W2 = (const float*)d_in[5];
    float* out = (float*)d_out;

    cudaFuncSetAttribute(gemm1_mma, cudaFuncAttributeMaxDynamicSharedMemorySize, G1_SMEM);
    cudaFuncSetAttribute(gemm2_mma, cudaFuncAttributeMaxDynamicSharedMemorySize, G2_SMEM);

    float *xt_p, *w1t_p, *w3t_p, *w2t_p;
    cudaGetSymbolAddress((void**)&xt_p,  g_xt);
    cudaGetSymbolAddress((void**)&w1t_p, g_w1t);
    cudaGetSymbolAddress((void**)&w3t_p, g_w3t);
    cudaGetSymbolAddress((void**)&w2t_p, g_w2t);

    const int wN4 = NE * HD * FF / 4;
    const int xN4 = TOK * HD / 4;

    round_tf32_kernel<<<(xN4 + 255) / 256, 256>>>((const float4*)x,  (float4*)xt_p,  xN4);
    round_tf32_kernel<<<(wN4 + 255) / 256, 256>>>((const float4*)W1, (float4*)w1t_p, wN4);
    round_tf32_kernel<<<(wN4 + 255) / 256, 256>>>((const float4*)W3, (float4*)w3t_p, wN4);
    round_tf32_kernel<<<(wN4 + 255) / 256, 256>>>((const float4*)W2, (float4*)w2t_p, wN4);

    zero_counts_kernel<<<1, 32>>>();
    routing_kernel<<<TOK, 256>>>(x, Wg, bg);
    bases_kernel<<<1, 1>>>();
    gemm1_mma<<<dim3(FF / 64, TOK / 128, NE), 256, G1_SMEM>>>();
    gemm2_mma<<<dim3(HD / 128, TOK / 128, NE), 256, G2_SMEM>>>();
    combine_kernel<<<(TOK * (HD / 4)) / 256, 256>>>(out);
}